// round 7
// baseline (speedup 1.0000x reference)
#include <cuda_runtime.h>
#include <cstdint>

// Problem constants
#define BB 4
#define SS 8192
#define DD 1024
#define KK 16
#define MTOT (BB * SS)        // 32768 tokens
#define TS_CHUNKS 64
#define TS_SLEN (SS / TS_CHUNKS)   // 128
#define MKD (BB * KK * DD)    // 65536
#define SG_ECHUNKS 32         // smallgemm e-chunks (32 e each)

// ---------------- scratch (device globals; no allocations) ------------------
__device__ float g_aff [(size_t)MTOT * KK];            // 2 MB
__device__ float g_tsp [(size_t)TS_CHUNKS * MKD];      // 16 MB  (ts partials)
__device__ float g_ts  [(size_t)MKD];                  // 256 KB (aff^T @ tok)
__device__ float g_ssp [(size_t)SG_ECHUNKS * MKD];     // 8 MB   (mini-gemm partials)
__device__ float g_ss  [(size_t)MKD];                  // 256 KB (ts @ W_v)
__device__ float g_ssw [(size_t)MKD];                  // 256 KB (ss @ W_o)
__device__ float g_params[32];                         // csq[16], m[16]

// ---------------- packed f32x2 helpers ---------------------------------------
#define FMA2(d, a, b) \
    asm("fma.rn.f32x2 %0, %1, %2, %0;" : "+l"(d) : "l"(a), "l"(b))
#define PACK2(dst, lo, hi) \
    asm("mov.b64 %0, {%1, %2};" : "=l"(dst) \
        : "r"(__float_as_uint(lo)), "r"(__float_as_uint(hi)))

typedef unsigned long long ull;

// ======================= kernel 0: per-splat params ==========================
__global__ __launch_bounds__(512)
void params_kernel(const float* __restrict__ centers,
                   const float* __restrict__ log_scales)
{
    const int w    = threadIdx.x >> 5;
    const int lane = threadIdx.x & 31;
    float s = 0.f;
    const float* c = centers + (size_t)w * DD;
    for (int d = lane; d < DD; d += 32) {
        float v = c[d];
        s = fmaf(v, v, s);
    }
    #pragma unroll
    for (int off = 16; off; off >>= 1)
        s += __shfl_xor_sync(0xffffffffu, s, off);
    if (lane == 0) {
        g_params[w] = s;
        float sc = expf(log_scales[w]);
        sc = fminf(fmaxf(sc, 0.1f), 2.0f);
        g_params[16 + w] = -0.5f / (sc * sc);
    }
}

// ======================= fused affinities + ts partials ======================
// grid (TS_CHUNKS, BB), block 256 (8 warps). Block owns 128 tokens.
// Phase A: FMA2-packed cross products, 4 tokens/warp-pass, K split in halves.
// Phase B: FMA2 ts partial accumulation (token chunk re-read hits L2).
__global__ __launch_bounds__(256, 2)
void fused_aff_ts_kernel(const float* __restrict__ tok,
                         const float* __restrict__ centers)
{
    __shared__ float2 saff[TS_SLEN][KK];   // normalized aff as (a,a) pairs, 16KB
    __shared__ float  scr [8][4][KK];      // per-warp cross results, 2KB

    const int tid  = threadIdx.x;
    const int w    = tid >> 5;
    const int lane = tid & 31;
    const int ck   = blockIdx.x;
    const int b    = blockIdx.y;
    const int s0   = ck * TS_SLEN;

    // ---------------- Phase A ----------------
    #pragma unroll 1
    for (int j = 0; j < 4; j++) {
        const int lt = w * 16 + j * 4;     // 4 tokens this pass
        const float* tb = tok + ((size_t)b * SS + s0 + lt) * DD;

        float tsq[4];

        #pragma unroll 1
        for (int kh = 0; kh < 2; kh++) {
            ull c2[4][8];
            ull t2[4];
            #pragma unroll
            for (int i = 0; i < 4; i++) {
                t2[i] = 0ull;
                #pragma unroll
                for (int kk = 0; kk < 8; kk++) c2[i][kk] = 0ull;
            }

            #pragma unroll 1
            for (int it = 0; it < 8; it++) {
                const int d = it * 128 + lane * 4;
                ulonglong2 tv[4];
                #pragma unroll
                for (int i = 0; i < 4; i++) {
                    tv[i] = *reinterpret_cast<const ulonglong2*>(
                        tb + (size_t)i * DD + d);
                    if (kh == 0) {
                        FMA2(t2[i], tv[i].x, tv[i].x);
                        FMA2(t2[i], tv[i].y, tv[i].y);
                    }
                }
                #pragma unroll
                for (int kk = 0; kk < 8; kk++) {
                    const ulonglong2 cv = *reinterpret_cast<const ulonglong2*>(
                        centers + (size_t)(kh * 8 + kk) * DD + d);
                    #pragma unroll
                    for (int i = 0; i < 4; i++) {
                        FMA2(c2[i][kk], tv[i].x, cv.x);
                        FMA2(c2[i][kk], tv[i].y, cv.y);
                    }
                }
            }

            // horizontal + butterfly reduce; publish per-(token,k) cross
            #pragma unroll
            for (int i = 0; i < 4; i++) {
                #pragma unroll
                for (int kk = 0; kk < 8; kk++) {
                    float2 p = *reinterpret_cast<float2*>(&c2[i][kk]);
                    float cr = p.x + p.y;
                    #pragma unroll
                    for (int off = 16; off; off >>= 1)
                        cr += __shfl_xor_sync(0xffffffffu, cr, off);
                    if (lane == 0) scr[w][i][kh * 8 + kk] = cr;
                }
                if (kh == 0) {
                    float2 q = *reinterpret_cast<float2*>(&t2[i]);
                    float ts_ = q.x + q.y;
                    #pragma unroll
                    for (int off = 16; off; off >>= 1)
                        ts_ += __shfl_xor_sync(0xffffffffu, ts_, off);
                    tsq[i] = ts_;
                }
            }
        }
        __syncwarp();

        // finalize the 4 tokens
        #pragma unroll
        for (int i = 0; i < 4; i++) {
            float a = 0.f;
            if (lane < KK) {
                float dist = fmaxf(tsq[i] - 2.f * scr[w][i][lane] + g_params[lane], 0.f);
                a = expf(g_params[16 + lane] * dist);
            }
            float ssum = a;
            #pragma unroll
            for (int off = 16; off; off >>= 1)
                ssum += __shfl_xor_sync(0xffffffffu, ssum, off);
            if (lane < KK) {
                const float an = a / (ssum + 1e-8f);
                saff[lt + i][lane] = make_float2(an, an);
                g_aff[((size_t)b * SS + s0 + lt + i) * KK + lane] = an;
            }
        }
        __syncwarp();
    }
    __syncthreads();

    // ---------------- Phase B: ts partial accumulation ----------------------
    const int d = tid * 4;
    const float* tp = tok + ((size_t)b * SS + s0) * DD + d;

    ull acc[KK][2];
    #pragma unroll
    for (int k = 0; k < KK; k++) { acc[k][0] = 0ull; acc[k][1] = 0ull; }

    #pragma unroll 2
    for (int s = 0; s < TS_SLEN; s++) {
        ulonglong2 v = *reinterpret_cast<const ulonglong2*>(tp + (size_t)s * DD);
        #pragma unroll
        for (int k = 0; k < KK; k++) {
            ull a = *reinterpret_cast<const ull*>(&saff[s][k]);
            FMA2(acc[k][0], a, v.x);
            FMA2(acc[k][1], a, v.y);
        }
    }

    float* op = g_tsp + (size_t)ck * MKD + ((size_t)b * KK) * DD + d;
    #pragma unroll
    for (int k = 0; k < KK; k++)
        *reinterpret_cast<ulonglong2*>(op + (size_t)k * DD) =
            make_ulonglong2(acc[k][0], acc[k][1]);
}

// ======================= vectorized partial reduce ===========================
// block 128, ILP-8 over partials
__global__ __launch_bounds__(128)
void reduce4_kernel(const float4* __restrict__ src, float4* __restrict__ dst,
                    int np, int len4)
{
    const int i = blockIdx.x * 128 + threadIdx.x;
    if (i >= len4) return;
    float4 a[8];
    #pragma unroll
    for (int q = 0; q < 8; q++) a[q] = make_float4(0, 0, 0, 0);
    int p = 0;
    for (; p + 8 <= np; p += 8) {
        #pragma unroll
        for (int q = 0; q < 8; q++) {
            float4 v = src[(size_t)(p + q) * len4 + i];
            a[q].x += v.x; a[q].y += v.y; a[q].z += v.z; a[q].w += v.w;
        }
    }
    for (; p < np; p++) {
        float4 v = src[(size_t)p * len4 + i];
        a[0].x += v.x; a[0].y += v.y; a[0].z += v.z; a[0].w += v.w;
    }
    #pragma unroll
    for (int q = 1; q < 8; q++) {
        a[0].x += a[q].x; a[0].y += a[q].y; a[0].z += a[q].z; a[0].w += a[q].w;
    }
    dst[i] = a[0];
}

// ======================= mini GEMM: ssp = M64[64,1024] @ W[1024,1024] ========
// grid (16 n-tiles, 32 e-chunks of 32); W loads software-pipelined 8 deep.
__global__ __launch_bounds__(256)
void smallgemm_kernel(const float* __restrict__ M64, const float* __restrict__ W)
{
    __shared__ float se[32][66];   // [e][m], padded
    const int tid = threadIdx.x;
    const int n0  = blockIdx.x * 64;
    const int e0  = blockIdx.y * 32;

    // stage: transpose M64 chunk [64 m][32 e] -> se[e][m]
    {
        const int m  = tid >> 2;
        const int ee = (tid & 3) * 8;
        const float* mp = M64 + (size_t)m * DD + e0 + ee;
        float4 v0 = *reinterpret_cast<const float4*>(mp);
        float4 v1 = *reinterpret_cast<const float4*>(mp + 4);
        se[ee + 0][m] = v0.x; se[ee + 1][m] = v0.y;
        se[ee + 2][m] = v0.z; se[ee + 3][m] = v0.w;
        se[ee + 4][m] = v1.x; se[ee + 5][m] = v1.y;
        se[ee + 6][m] = v1.z; se[ee + 7][m] = v1.w;
    }
    __syncthreads();

    const int nq = tid & 63;        // column n0 + nq
    const int mg = tid >> 6;        // m group: rows mg*16 .. mg*16+15
    const float* wp = W + (size_t)e0 * DD + n0 + nq;

    ull acc[8];
    #pragma unroll
    for (int j = 0; j < 8; j++) acc[j] = 0ull;

    // software pipeline: 8 W values in flight
    float wv[8], nv[8];
    #pragma unroll
    for (int q = 0; q < 8; q++) wv[q] = wp[(size_t)q * DD];

    #pragma unroll
    for (int e = 0; e < 32; e += 8) {
        if (e + 8 < 32) {
            #pragma unroll
            for (int q = 0; q < 8; q++) nv[q] = wp[(size_t)(e + 8 + q) * DD];
        }
        #pragma unroll
        for (int q = 0; q < 8; q++) {
            ull wd;
            PACK2(wd, wv[q], wv[q]);
            #pragma unroll
            for (int j = 0; j < 8; j++) {
                ull a = *reinterpret_cast<const ull*>(&se[e + q][mg * 16 + 2 * j]);
                FMA2(acc[j], a, wd);
            }
        }
        #pragma unroll
        for (int q = 0; q < 8; q++) wv[q] = nv[q];
    }

    float* dst = g_ssp + (size_t)blockIdx.y * MKD + n0 + nq;
    #pragma unroll
    for (int j = 0; j < 8; j++) {
        float2 p = *reinterpret_cast<float2*>(&acc[j]);
        dst[(size_t)(mg * 16 + 2 * j)     * DD] = p.x;
        dst[(size_t)(mg * 16 + 2 * j + 1) * DD] = p.y;
    }
}

// ======================= out = aff @ ssw =====================================
// grid (SS/128, BB), block 256. aff transposed in smem [k][t]; inner loop
// processes a 2-token x 2-d group: 16 broadcast LDS.64 + 32 FMA2.
__global__ __launch_bounds__(256)
void out_mix_kernel(float* __restrict__ out)
{
    __shared__ float saT[KK][128];   // 8KB, aff transposed
    const int tid  = threadIdx.x;
    const int wid  = tid >> 5;
    const int lane = tid & 31;
    const int b    = blockIdx.y;
    const int s0   = blockIdx.x * 128;

    // stage aff (coalesced, transposed): 128 tokens x 16 k
    {
        const float* ap = g_aff + ((size_t)b * SS + s0) * KK;
        #pragma unroll
        for (int it = 0; it < 2; it++) {
            const int i = tid + it * 256;          // 0..511
            float4 v = *reinterpret_cast<const float4*>(ap + i * 4);
            const int t  = i >> 2;
            const int kg = (i & 3) * 4;
            saT[kg + 0][t] = v.x;
            saT[kg + 1][t] = v.y;
            saT[kg + 2][t] = v.z;
            saT[kg + 3][t] = v.w;
        }
    }
    __syncthreads();

    #pragma unroll 1
    for (int pass = 0; pass < 2; pass++) {
        const int d0 = pass * 512 + wid * 64 + lane * 2;

        // duplicated ssw pairs for this thread's 2 d-columns
        ull wd0[KK], wd1[KK];
        #pragma unroll
        for (int k = 0; k < KK; k++) {
            float2 wv = *reinterpret_cast<const float2*>(
                g_ssw + ((size_t)(b * KK + k)) * DD + d0);
            PACK2(wd0[k], wv.x, wv.x);
            PACK2(wd1[k], wv.y, wv.y);
        }

        float* op = out + ((size_t)b * SS + s0) * DD + d0;

        #pragma unroll 2
        for (int t = 0; t < 128; t += 2) {
            ull acc0 = 0ull, acc1 = 0ull;
            #pragma unroll
            for (int k = 0; k < KK; k++) {
                ull a = *reinterpret_cast<const ull*>(&saT[k][t]);  // (aff[t], aff[t+1])
                FMA2(acc0, a, wd0[k]);
                FMA2(acc1, a, wd1[k]);
            }
            float2 p0 = *reinterpret_cast<float2*>(&acc0);
            float2 p1 = *reinterpret_cast<float2*>(&acc1);
            *reinterpret_cast<float2*>(op + (size_t)t * DD)       = make_float2(p0.x, p1.x);
            *reinterpret_cast<float2*>(op + (size_t)(t + 1) * DD) = make_float2(p0.y, p1.y);
        }
    }
}

// ======================= launch ==============================================
extern "C" void kernel_launch(void* const* d_in, const int* in_sizes, int n_in,
                              void* d_out, int out_size)
{
    const float* tok     = (const float*)d_in[0];
    const float* centers = (const float*)d_in[1];
    const float* logs    = (const float*)d_in[2];
    const float* Wv      = (const float*)d_in[3];
    const float* Wo      = (const float*)d_in[4];
    float* out = (float*)d_out;

    float *tsp, *ts, *ssp, *ss, *ssw;
    cudaGetSymbolAddress((void**)&tsp, g_tsp);
    cudaGetSymbolAddress((void**)&ts,  g_ts);
    cudaGetSymbolAddress((void**)&ssp, g_ssp);
    cudaGetSymbolAddress((void**)&ss,  g_ss);
    cudaGetSymbolAddress((void**)&ssw, g_ssw);

    params_kernel<<<1, 512>>>(centers, logs);

    // aff + ts partials fused (single DRAM pass over tokens)
    fused_aff_ts_kernel<<<dim3(TS_CHUNKS, BB), 256>>>(tok, centers);
    reduce4_kernel<<<(MKD / 4) / 128, 128>>>(
        (const float4*)tsp, (float4*)ts, TS_CHUNKS, MKD / 4);

    // ss = ts @ W_v
    smallgemm_kernel<<<dim3(16, SG_ECHUNKS), 256>>>(ts, Wv);
    reduce4_kernel<<<(MKD / 4) / 128, 128>>>(
        (const float4*)ssp, (float4*)ss, SG_ECHUNKS, MKD / 4);

    // ssw = ss @ W_o
    smallgemm_kernel<<<dim3(16, SG_ECHUNKS), 256>>>(ss, Wo);
    reduce4_kernel<<<(MKD / 4) / 128, 128>>>(
        (const float4*)ssp, (float4*)ssw, SG_ECHUNKS, MKD / 4);

    // out = aff @ ssw
    out_mix_kernel<<<dim3(SS / 128, BB), 256>>>(out);
}

// round 8
// speedup vs baseline: 1.0487x; 1.0487x over previous
#include <cuda_runtime.h>
#include <cstdint>

// Problem constants
#define BB 4
#define SS 8192
#define DD 1024
#define KK 16
#define MTOT (BB * SS)        // 32768 tokens
#define TS_CHUNKS 64
#define TS_SLEN (SS / TS_CHUNKS)   // 128
#define MKD (BB * KK * DD)    // 65536
#define SG_ECHUNKS 32         // smallgemm e-chunks (32 e each)

// ---------------- scratch (device globals; no allocations) ------------------
__device__ float g_aff [(size_t)MTOT * KK];            // 2 MB
__device__ float g_tsp [(size_t)TS_CHUNKS * MKD];      // 16 MB  (ts partials)
__device__ float g_ts  [(size_t)MKD];                  // 256 KB (aff^T @ tok)
__device__ float g_ssp [(size_t)SG_ECHUNKS * MKD];     // 8 MB   (mini-gemm partials)
__device__ float g_ss  [(size_t)MKD];                  // 256 KB (ts @ W_v)
__device__ float g_ssw [(size_t)MKD];                  // 256 KB (ss @ W_o)
__device__ float g_params[32];                         // csq[16], m[16]

// ---------------- packed f32x2 helpers ---------------------------------------
#define FMA2(d, a, b) \
    asm("fma.rn.f32x2 %0, %1, %2, %0;" : "+l"(d) : "l"(a), "l"(b))
#define PACK2(dst, lo, hi) \
    asm("mov.b64 %0, {%1, %2};" : "=l"(dst) \
        : "r"(__float_as_uint(lo)), "r"(__float_as_uint(hi)))

typedef unsigned long long ull;

// ======================= kernel 0: per-splat params ==========================
__global__ __launch_bounds__(512)
void params_kernel(const float* __restrict__ centers,
                   const float* __restrict__ log_scales)
{
    const int w    = threadIdx.x >> 5;
    const int lane = threadIdx.x & 31;
    float s = 0.f;
    const float* c = centers + (size_t)w * DD;
    for (int d = lane; d < DD; d += 32) {
        float v = c[d];
        s = fmaf(v, v, s);
    }
    #pragma unroll
    for (int off = 16; off; off >>= 1)
        s += __shfl_xor_sync(0xffffffffu, s, off);
    if (lane == 0) {
        g_params[w] = s;
        float sc = expf(log_scales[w]);
        sc = fminf(fmaxf(sc, 0.1f), 2.0f);
        g_params[16 + w] = -0.5f / (sc * sc);
    }
}

// ======================= fused affinities + ts partials ======================
// grid (TS_CHUNKS, BB), block 256 (8 warps). Block owns 128 tokens.
// (R6 version — known good)
__global__ __launch_bounds__(256, 2)
void fused_aff_ts_kernel(const float* __restrict__ tok,
                         const float* __restrict__ centers)
{
    __shared__ float2 saff[TS_SLEN][KK];   // normalized aff as (a,a) pairs, 16KB
    __shared__ float  scr [8][16];

    const int tid  = threadIdx.x;
    const int w    = tid >> 5;
    const int lane = tid & 31;
    const int ck   = blockIdx.x;
    const int b    = blockIdx.y;
    const int s0   = ck * TS_SLEN;

    // ---------------- Phase A: affinities, 4 tokens per pass ----------------
    #pragma unroll 1
    for (int j = 0; j < 4; j++) {
        const int lt = w * 16 + j * 4;
        const float* tb = tok + ((size_t)b * SS + s0 + lt) * DD;

        float cross[4][KK];
        float tsq[4];
        #pragma unroll
        for (int i = 0; i < 4; i++) {
            tsq[i] = 0.f;
            #pragma unroll
            for (int k = 0; k < KK; k++) cross[i][k] = 0.f;
        }

        #pragma unroll 1
        for (int it = 0; it < DD / 128; it++) {
            const int d = it * 128 + lane * 4;
            float4 tv[4];
            #pragma unroll
            for (int i = 0; i < 4; i++) {
                tv[i] = *reinterpret_cast<const float4*>(tb + (size_t)i * DD + d);
                tsq[i] = fmaf(tv[i].x, tv[i].x, fmaf(tv[i].y, tv[i].y,
                          fmaf(tv[i].z, tv[i].z, fmaf(tv[i].w, tv[i].w, tsq[i]))));
            }
            #pragma unroll
            for (int k = 0; k < KK; k++) {
                const float4 cv = __ldg(reinterpret_cast<const float4*>(
                    centers + (size_t)k * DD + d));
                #pragma unroll
                for (int i = 0; i < 4; i++)
                    cross[i][k] = fmaf(tv[i].x, cv.x, fmaf(tv[i].y, cv.y,
                                   fmaf(tv[i].z, cv.z, fmaf(tv[i].w, cv.w, cross[i][k]))));
            }
        }

        #pragma unroll
        for (int i = 0; i < 4; i++) {
            #pragma unroll
            for (int k = 0; k < KK; k++) {
                #pragma unroll
                for (int off = 16; off; off >>= 1)
                    cross[i][k] += __shfl_xor_sync(0xffffffffu, cross[i][k], off);
            }
            #pragma unroll
            for (int off = 16; off; off >>= 1)
                tsq[i] += __shfl_xor_sync(0xffffffffu, tsq[i], off);
        }

        #pragma unroll
        for (int i = 0; i < 4; i++) {
            if (lane == 0) {
                #pragma unroll
                for (int k = 0; k < KK; k++) scr[w][k] = cross[i][k];
            }
            __syncwarp();
            float a = 0.f;
            if (lane < KK) {
                float dist = fmaxf(tsq[i] - 2.f * scr[w][lane] + g_params[lane], 0.f);
                a = expf(g_params[16 + lane] * dist);
            }
            float ssum = a;
            #pragma unroll
            for (int off = 16; off; off >>= 1)
                ssum += __shfl_xor_sync(0xffffffffu, ssum, off);
            if (lane < KK) {
                const float an = a / (ssum + 1e-8f);
                saff[lt + i][lane] = make_float2(an, an);
                g_aff[((size_t)b * SS + s0 + lt + i) * KK + lane] = an;
            }
            __syncwarp();
        }
    }
    __syncthreads();

    // ---------------- Phase B: ts partial accumulation ----------------------
    const int d = tid * 4;
    const float* tp = tok + ((size_t)b * SS + s0) * DD + d;

    ull acc[KK][2];
    #pragma unroll
    for (int k = 0; k < KK; k++) { acc[k][0] = 0ull; acc[k][1] = 0ull; }

    #pragma unroll 2
    for (int s = 0; s < TS_SLEN; s++) {
        float4 v = *reinterpret_cast<const float4*>(tp + (size_t)s * DD);
        ull vlo, vhi;
        PACK2(vlo, v.x, v.y);
        PACK2(vhi, v.z, v.w);
        #pragma unroll
        for (int k = 0; k < KK; k++) {
            ull a = *reinterpret_cast<const ull*>(&saff[s][k]);
            FMA2(acc[k][0], a, vlo);
            FMA2(acc[k][1], a, vhi);
        }
    }

    float* op = g_tsp + (size_t)ck * MKD + ((size_t)b * KK) * DD + d;
    #pragma unroll
    for (int k = 0; k < KK; k++)
        *reinterpret_cast<ulonglong2*>(op + (size_t)k * DD) =
            make_ulonglong2(acc[k][0], acc[k][1]);
}

// ======================= vectorized partial reduce (R6) ======================
__global__ __launch_bounds__(256)
void reduce4_kernel(const float4* __restrict__ src, float4* __restrict__ dst,
                    int np, int len4)
{
    const int i = blockIdx.x * 256 + threadIdx.x;
    if (i >= len4) return;
    float4 a0 = make_float4(0,0,0,0), a1 = a0, a2 = a0, a3 = a0;
    int p = 0;
    for (; p + 4 <= np; p += 4) {
        float4 v0 = src[(size_t)(p + 0) * len4 + i];
        float4 v1 = src[(size_t)(p + 1) * len4 + i];
        float4 v2 = src[(size_t)(p + 2) * len4 + i];
        float4 v3 = src[(size_t)(p + 3) * len4 + i];
        a0.x += v0.x; a0.y += v0.y; a0.z += v0.z; a0.w += v0.w;
        a1.x += v1.x; a1.y += v1.y; a1.z += v1.z; a1.w += v1.w;
        a2.x += v2.x; a2.y += v2.y; a2.z += v2.z; a2.w += v2.w;
        a3.x += v3.x; a3.y += v3.y; a3.z += v3.z; a3.w += v3.w;
    }
    for (; p < np; p++) {
        float4 v = src[(size_t)p * len4 + i];
        a0.x += v.x; a0.y += v.y; a0.z += v.z; a0.w += v.w;
    }
    dst[i] = make_float4(a0.x + a1.x + a2.x + a3.x,
                         a0.y + a1.y + a2.y + a3.y,
                         a0.z + a1.z + a2.z + a3.z,
                         a0.w + a1.w + a2.w + a3.w);
}

// ======================= mini GEMM (R6) ======================================
__global__ __launch_bounds__(256)
void smallgemm_kernel(const float* __restrict__ M64, const float* __restrict__ W)
{
    __shared__ float se[32][66];   // [e][m], padded
    const int tid = threadIdx.x;
    const int n0  = blockIdx.x * 64;
    const int e0  = blockIdx.y * 32;

    {
        const int m  = tid >> 2;
        const int ee = (tid & 3) * 8;
        const float* mp = M64 + (size_t)m * DD + e0 + ee;
        float4 v0 = *reinterpret_cast<const float4*>(mp);
        float4 v1 = *reinterpret_cast<const float4*>(mp + 4);
        se[ee + 0][m] = v0.x; se[ee + 1][m] = v0.y;
        se[ee + 2][m] = v0.z; se[ee + 3][m] = v0.w;
        se[ee + 4][m] = v1.x; se[ee + 5][m] = v1.y;
        se[ee + 6][m] = v1.z; se[ee + 7][m] = v1.w;
    }
    __syncthreads();

    const int nq = tid & 63;
    const int mg = tid >> 6;
    const float* wp = W + (size_t)e0 * DD + n0 + nq;

    ull acc[8];
    #pragma unroll
    for (int j = 0; j < 8; j++) acc[j] = 0ull;

    float wv[4], nv[4];
    #pragma unroll
    for (int q = 0; q < 4; q++) wv[q] = wp[(size_t)q * DD];

    #pragma unroll
    for (int e = 0; e < 32; e += 4) {
        if (e + 4 < 32) {
            #pragma unroll
            for (int q = 0; q < 4; q++) nv[q] = wp[(size_t)(e + 4 + q) * DD];
        }
        #pragma unroll
        for (int q = 0; q < 4; q++) {
            ull wd;
            PACK2(wd, wv[q], wv[q]);
            #pragma unroll
            for (int j = 0; j < 8; j++) {
                ull a = *reinterpret_cast<const ull*>(&se[e + q][mg * 16 + 2 * j]);
                FMA2(acc[j], a, wd);
            }
        }
        #pragma unroll
        for (int q = 0; q < 4; q++) wv[q] = nv[q];
    }

    float* dst = g_ssp + (size_t)blockIdx.y * MKD + n0 + nq;
    #pragma unroll
    for (int j = 0; j < 8; j++) {
        float2 p = *reinterpret_cast<float2*>(&acc[j]);
        dst[(size_t)(mg * 16 + 2 * j)     * DD] = p.x;
        dst[(size_t)(mg * 16 + 2 * j + 1) * DD] = p.y;
    }
}

// ======================= out = aff @ ssw (token-pair packed) =================
// grid (SS/128, BB), block 256. aff transposed in smem [k][t]; inner loop
// processes a 2-token x 2-d group: 16 broadcast LDS.64 + 32 FMA2.
__global__ __launch_bounds__(256)
void out_mix_kernel(float* __restrict__ out)
{
    __shared__ float saT[KK][128];   // 8KB, aff transposed
    const int tid  = threadIdx.x;
    const int wid  = tid >> 5;
    const int lane = tid & 31;
    const int b    = blockIdx.y;
    const int s0   = blockIdx.x * 128;

    // stage aff (coalesced, transposed): 128 tokens x 16 k
    {
        const float* ap = g_aff + ((size_t)b * SS + s0) * KK;
        #pragma unroll
        for (int it = 0; it < 2; it++) {
            const int i = tid + it * 256;          // 0..511
            float4 v = *reinterpret_cast<const float4*>(ap + i * 4);
            const int t  = i >> 2;
            const int kg = (i & 3) * 4;
            saT[kg + 0][t] = v.x;
            saT[kg + 1][t] = v.y;
            saT[kg + 2][t] = v.z;
            saT[kg + 3][t] = v.w;
        }
    }
    __syncthreads();

    #pragma unroll 1
    for (int pass = 0; pass < 2; pass++) {
        const int d0 = pass * 512 + wid * 64 + lane * 2;

        // duplicated ssw pairs for this thread's 2 d-columns
        ull wd0[KK], wd1[KK];
        #pragma unroll
        for (int k = 0; k < KK; k++) {
            float2 wv = *reinterpret_cast<const float2*>(
                g_ssw + ((size_t)(b * KK + k)) * DD + d0);
            PACK2(wd0[k], wv.x, wv.x);
            PACK2(wd1[k], wv.y, wv.y);
        }

        float* op = out + ((size_t)b * SS + s0) * DD + d0;

        #pragma unroll 2
        for (int t = 0; t < 128; t += 2) {
            ull acc0 = 0ull, acc1 = 0ull;
            #pragma unroll
            for (int k = 0; k < KK; k++) {
                ull a = *reinterpret_cast<const ull*>(&saT[k][t]);  // (aff[t], aff[t+1])
                FMA2(acc0, a, wd0[k]);
                FMA2(acc1, a, wd1[k]);
            }
            float2 p0 = *reinterpret_cast<float2*>(&acc0);
            float2 p1 = *reinterpret_cast<float2*>(&acc1);
            *reinterpret_cast<float2*>(op + (size_t)t * DD)       = make_float2(p0.x, p1.x);
            *reinterpret_cast<float2*>(op + (size_t)(t + 1) * DD) = make_float2(p0.y, p1.y);
        }
    }
}

// ======================= launch ==============================================
extern "C" void kernel_launch(void* const* d_in, const int* in_sizes, int n_in,
                              void* d_out, int out_size)
{
    const float* tok     = (const float*)d_in[0];
    const float* centers = (const float*)d_in[1];
    const float* logs    = (const float*)d_in[2];
    const float* Wv      = (const float*)d_in[3];
    const float* Wo      = (const float*)d_in[4];
    float* out = (float*)d_out;

    float *tsp, *ts, *ssp, *ss, *ssw;
    cudaGetSymbolAddress((void**)&tsp, g_tsp);
    cudaGetSymbolAddress((void**)&ts,  g_ts);
    cudaGetSymbolAddress((void**)&ssp, g_ssp);
    cudaGetSymbolAddress((void**)&ss,  g_ss);
    cudaGetSymbolAddress((void**)&ssw, g_ssw);

    params_kernel<<<1, 512>>>(centers, logs);

    // aff + ts partials fused (single DRAM pass over tokens)
    fused_aff_ts_kernel<<<dim3(TS_CHUNKS, BB), 256>>>(tok, centers);
    reduce4_kernel<<<(MKD / 4 + 255) / 256, 256>>>(
        (const float4*)tsp, (float4*)ts, TS_CHUNKS, MKD / 4);

    // ss = ts @ W_v
    smallgemm_kernel<<<dim3(16, SG_ECHUNKS), 256>>>(ts, Wv);
    reduce4_kernel<<<(MKD / 4 + 255) / 256, 256>>>(
        (const float4*)ssp, (float4*)ss, SG_ECHUNKS, MKD / 4);

    // ssw = ss @ W_o
    smallgemm_kernel<<<dim3(16, SG_ECHUNKS), 256>>>(ss, Wo);
    reduce4_kernel<<<(MKD / 4 + 255) / 256, 256>>>(
        (const float4*)ssp, (float4*)ssw, SG_ECHUNKS, MKD / 4);

    // out = aff @ ssw
    out_mix_kernel<<<dim3(SS / 128, BB), 256>>>(out);
}

// round 9
// speedup vs baseline: 1.2155x; 1.1591x over previous
#include <cuda_runtime.h>
#include <cstdint>

// Problem constants
#define BB 4
#define SS 8192
#define DD 1024
#define KK 16
#define MTOT (BB * SS)        // 32768 tokens
#define TS_CHUNKS 64
#define TS_SLEN (SS / TS_CHUNKS)   // 128
#define MKD (BB * KK * DD)    // 65536
#define SG_ECHUNKS 32         // smallgemm e-chunks (32 e each)

// ---------------- scratch (device globals; no allocations) ------------------
__device__ float g_aff [(size_t)MTOT * KK];            // 2 MB
__device__ float g_tsp [(size_t)TS_CHUNKS * MKD];      // 16 MB  (ts partials)
__device__ float g_ts  [(size_t)MKD];                  // 256 KB (aff^T @ tok)
__device__ float g_ssp [(size_t)SG_ECHUNKS * MKD];     // 8 MB   (mini-gemm partials)
__device__ float g_ss  [(size_t)MKD];                  // 256 KB (ts @ W_v)
__device__ float g_ssw [(size_t)MKD];                  // 256 KB (ss @ W_o)
__device__ float g_params[32];                         // csq[16], m[16]

// ---------------- packed f32x2 helpers ---------------------------------------
#define FMA2(d, a, b) \
    asm("fma.rn.f32x2 %0, %1, %2, %0;" : "+l"(d) : "l"(a), "l"(b))
#define PACK2(dst, lo, hi) \
    asm("mov.b64 %0, {%1, %2};" : "=l"(dst) \
        : "r"(__float_as_uint(lo)), "r"(__float_as_uint(hi)))

typedef unsigned long long ull;

__device__ __forceinline__ uint32_t smem_to_u32(const void* smem_ptr) {
    uint32_t addr;
    asm("{ .reg .u64 tmp; cvta.to.shared.u64 tmp, %1; cvt.u32.u64 %0, tmp; }"
        : "=r"(addr) : "l"(smem_ptr));
    return addr;
}
__device__ __forceinline__ uint32_t f2tf32(float x) {
    uint32_t r;
    asm("cvt.rn.tf32.f32 %0, %1;" : "=r"(r) : "f"(x));
    return r;
}
#define CP_ASYNC16(dst_u32, src_ptr) \
    asm volatile("cp.async.ca.shared.global [%0], [%1], 16;" \
        :: "r"(dst_u32), "l"(src_ptr) : "memory")
#define CP_COMMIT() asm volatile("cp.async.commit_group;" ::: "memory")
#define CP_WAIT1()  asm volatile("cp.async.wait_group 1;" ::: "memory")
#define CP_WAIT0()  asm volatile("cp.async.wait_group 0;" ::: "memory")

__device__ __forceinline__ void mma_tf32(float* c, const uint32_t* a, const uint32_t* b) {
    asm volatile(
        "mma.sync.aligned.m16n8k8.row.col.f32.tf32.tf32.f32 "
        "{%0,%1,%2,%3}, {%4,%5,%6,%7}, {%8,%9}, {%0,%1,%2,%3};\n"
        : "+f"(c[0]), "+f"(c[1]), "+f"(c[2]), "+f"(c[3])
        : "r"(a[0]), "r"(a[1]), "r"(a[2]), "r"(a[3]), "r"(b[0]), "r"(b[1]));
}

// ======================= kernel 0: per-splat params ==========================
__global__ __launch_bounds__(512)
void params_kernel(const float* __restrict__ centers,
                   const float* __restrict__ log_scales)
{
    const int w    = threadIdx.x >> 5;
    const int lane = threadIdx.x & 31;
    float s = 0.f;
    const float* c = centers + (size_t)w * DD;
    for (int d = lane; d < DD; d += 32) {
        float v = c[d];
        s = fmaf(v, v, s);
    }
    #pragma unroll
    for (int off = 16; off; off >>= 1)
        s += __shfl_xor_sync(0xffffffffu, s, off);
    if (lane == 0) {
        g_params[w] = s;
        float sc = expf(log_scales[w]);
        sc = fminf(fmaxf(sc, 0.1f), 2.0f);
        g_params[16 + w] = -0.5f / (sc * sc);
    }
}

// ======================= cross + affinities via mma.sync =====================
// grid MTOT/128, block 256 (8 warps). Warp owns 16 tokens x 16 splats.
// cross = tok @ centers^T on tensor pipe (tf32); tsq in fp32 during frag loads;
// affinity finalized in-register, written to g_aff.
#define XLDP 36
#define XA_WORDS (128 * XLDP)          // 4608 floats
#define XB_WORDS (16 * XLDP)           // 576 floats
#define XBUF (XA_WORDS + XB_WORDS)     // 5184 floats = 20736 B per buffer

__global__ __launch_bounds__(256)
void cross_aff_kernel(const float* __restrict__ tok,
                      const float* __restrict__ centers)
{
    __shared__ float xs[2 * XBUF];     // ~41.5 KB static

    const int tid  = threadIdx.x;
    const int w    = tid >> 5;
    const int lane = tid & 31;
    const int grp  = lane >> 2;        // 0..7
    const int tig  = lane & 3;         // 0..3
    const int bm   = blockIdx.x * 128; // token base
    const int wm16 = w * 16;           // warp token offset in block

    const uint32_t sbase = smem_to_u32(xs);

    float acc[2][4];                   // [nf][frag]
    #pragma unroll
    for (int nf = 0; nf < 2; nf++)
        #pragma unroll
        for (int q = 0; q < 4; q++) acc[nf][q] = 0.f;
    float sq0 = 0.f, sq1 = 0.f;        // tsq partials (rows grp, grp+8)

    // prologue loads: buffer 0, k0 = 0
    {
        #pragma unroll
        for (int i = 0; i < 4; i++) {
            const int id  = tid + i * 256;
            const int row = id >> 3;
            const int c4  = id & 7;
            CP_ASYNC16(sbase + (uint32_t)(row * XLDP + c4 * 4) * 4,
                       tok + (size_t)(bm + row) * DD + c4 * 4);
        }
        if (tid < 128) {
            const int row = tid >> 3;
            const int c4  = tid & 7;
            CP_ASYNC16(sbase + (uint32_t)(XA_WORDS + row * XLDP + c4 * 4) * 4,
                       centers + (size_t)row * DD + c4 * 4);
        }
        CP_COMMIT();
    }

    for (int kc = 0; kc < DD / 32; kc++) {
        const int cur = kc & 1;
        if (kc + 1 < DD / 32) {
            const int nxt = cur ^ 1;
            const uint32_t nb = sbase + (uint32_t)nxt * XBUF * 4;
            const int k0 = (kc + 1) * 32;
            #pragma unroll
            for (int i = 0; i < 4; i++) {
                const int id  = tid + i * 256;
                const int row = id >> 3;
                const int c4  = id & 7;
                CP_ASYNC16(nb + (uint32_t)(row * XLDP + c4 * 4) * 4,
                           tok + (size_t)(bm + row) * DD + k0 + c4 * 4);
            }
            if (tid < 128) {
                const int row = tid >> 3;
                const int c4  = tid & 7;
                CP_ASYNC16(nb + (uint32_t)(XA_WORDS + row * XLDP + c4 * 4) * 4,
                           centers + (size_t)row * DD + k0 + c4 * 4);
            }
            CP_COMMIT();
            CP_WAIT1();
        } else {
            CP_WAIT0();
        }
        __syncthreads();

        const float* As = xs + (size_t)cur * XBUF;
        const float* Bs = As + XA_WORDS;

        #pragma unroll
        for (int ks = 0; ks < 4; ks++) {
            const int kq = ks * 8 + tig;
            const float a0 = As[(wm16 + grp)     * XLDP + kq];
            const float a1 = As[(wm16 + grp + 8) * XLDP + kq];
            const float a2 = As[(wm16 + grp)     * XLDP + kq + 4];
            const float a3 = As[(wm16 + grp + 8) * XLDP + kq + 4];
            sq0 = fmaf(a0, a0, fmaf(a2, a2, sq0));
            sq1 = fmaf(a1, a1, fmaf(a3, a3, sq1));
            uint32_t af[4] = {f2tf32(a0), f2tf32(a1), f2tf32(a2), f2tf32(a3)};
            #pragma unroll
            for (int nf = 0; nf < 2; nf++) {
                const int cidx = nf * 8 + grp;
                uint32_t bf[2] = {f2tf32(Bs[cidx * XLDP + kq]),
                                  f2tf32(Bs[cidx * XLDP + kq + 4])};
                mma_tf32(acc[nf], af, bf);
            }
        }
        __syncthreads();
    }

    // tsq: reduce over the 4 tig lanes (cols) within each quad
    sq0 += __shfl_xor_sync(0xffffffffu, sq0, 1);
    sq0 += __shfl_xor_sync(0xffffffffu, sq0, 2);
    sq1 += __shfl_xor_sync(0xffffffffu, sq1, 1);
    sq1 += __shfl_xor_sync(0xffffffffu, sq1, 2);

    // affinity: rows t0 = bm+wm16+grp (acc[nf][0,1]) and t1 = t0+8 (acc[nf][2,3])
    // cols: nf*8 + tig*2 + {0,1}
    float e0[4], e1[4];               // [nf*2 + j]
    #pragma unroll
    for (int nf = 0; nf < 2; nf++) {
        #pragma unroll
        for (int j = 0; j < 2; j++) {
            const int col = nf * 8 + tig * 2 + j;
            const float csq = g_params[col];
            const float m   = g_params[16 + col];
            float d0 = fmaxf(sq0 - 2.f * acc[nf][j]     + csq, 0.f);
            float d1 = fmaxf(sq1 - 2.f * acc[nf][2 + j] + csq, 0.f);
            e0[nf * 2 + j] = expf(m * d0);
            e1[nf * 2 + j] = expf(m * d1);
        }
    }
    float s0 = e0[0] + e0[1] + e0[2] + e0[3];
    float s1 = e1[0] + e1[1] + e1[2] + e1[3];
    s0 += __shfl_xor_sync(0xffffffffu, s0, 1);
    s0 += __shfl_xor_sync(0xffffffffu, s0, 2);
    s1 += __shfl_xor_sync(0xffffffffu, s1, 1);
    s1 += __shfl_xor_sync(0xffffffffu, s1, 2);
    const float r0 = 1.f / (s0 + 1e-8f);
    const float r1 = 1.f / (s1 + 1e-8f);

    const int t0 = bm + wm16 + grp;
    #pragma unroll
    for (int nf = 0; nf < 2; nf++) {
        *reinterpret_cast<float2*>(g_aff + (size_t)t0 * KK + nf * 8 + tig * 2) =
            make_float2(e0[nf * 2] * r0, e0[nf * 2 + 1] * r0);
        *reinterpret_cast<float2*>(g_aff + (size_t)(t0 + 8) * KK + nf * 8 + tig * 2) =
            make_float2(e1[nf * 2] * r1, e1[nf * 2 + 1] * r1);
    }
}

// ======================= ts partials = aff^T @ tok ===========================
// grid (TS_CHUNKS, BB), block 256. Block owns 128 tokens. (R6 phase B)
__global__ __launch_bounds__(256, 2)
void ts_partial_kernel(const float* __restrict__ tok)
{
    __shared__ float2 saff[TS_SLEN][KK];   // aff as (a,a) pairs, 16KB
    const int tid = threadIdx.x;
    const int ck  = blockIdx.x;
    const int b   = blockIdx.y;
    const int s0  = ck * TS_SLEN;

    // stage aff chunk: 2048 floats, coalesced
    {
        const float* ap = g_aff + ((size_t)b * SS + s0) * KK;
        #pragma unroll
        for (int it = 0; it < 2; it++) {
            const int i = tid + it * 256;      // 0..511 (float4 index)
            float4 v = *reinterpret_cast<const float4*>(ap + i * 4);
            const int t  = i >> 2;
            const int kg = (i & 3) * 4;
            saff[t][kg + 0] = make_float2(v.x, v.x);
            saff[t][kg + 1] = make_float2(v.y, v.y);
            saff[t][kg + 2] = make_float2(v.z, v.z);
            saff[t][kg + 3] = make_float2(v.w, v.w);
        }
    }
    __syncthreads();

    const int d = tid * 4;
    const float* tp = tok + ((size_t)b * SS + s0) * DD + d;

    ull acc[KK][2];
    #pragma unroll
    for (int k = 0; k < KK; k++) { acc[k][0] = 0ull; acc[k][1] = 0ull; }

    #pragma unroll 2
    for (int s = 0; s < TS_SLEN; s++) {
        float4 v = *reinterpret_cast<const float4*>(tp + (size_t)s * DD);
        ull vlo, vhi;
        PACK2(vlo, v.x, v.y);
        PACK2(vhi, v.z, v.w);
        #pragma unroll
        for (int k = 0; k < KK; k++) {
            ull a = *reinterpret_cast<const ull*>(&saff[s][k]);
            FMA2(acc[k][0], a, vlo);
            FMA2(acc[k][1], a, vhi);
        }
    }

    float* op = g_tsp + (size_t)ck * MKD + ((size_t)b * KK) * DD + d;
    #pragma unroll
    for (int k = 0; k < KK; k++)
        *reinterpret_cast<ulonglong2*>(op + (size_t)k * DD) =
            make_ulonglong2(acc[k][0], acc[k][1]);
}

// ======================= vectorized partial reduce ===========================
__global__ __launch_bounds__(256)
void reduce4_kernel(const float4* __restrict__ src, float4* __restrict__ dst,
                    int np, int len4)
{
    const int i = blockIdx.x * 256 + threadIdx.x;
    if (i >= len4) return;
    float4 a0 = make_float4(0,0,0,0), a1 = a0, a2 = a0, a3 = a0;
    int p = 0;
    for (; p + 4 <= np; p += 4) {
        float4 v0 = src[(size_t)(p + 0) * len4 + i];
        float4 v1 = src[(size_t)(p + 1) * len4 + i];
        float4 v2 = src[(size_t)(p + 2) * len4 + i];
        float4 v3 = src[(size_t)(p + 3) * len4 + i];
        a0.x += v0.x; a0.y += v0.y; a0.z += v0.z; a0.w += v0.w;
        a1.x += v1.x; a1.y += v1.y; a1.z += v1.z; a1.w += v1.w;
        a2.x += v2.x; a2.y += v2.y; a2.z += v2.z; a2.w += v2.w;
        a3.x += v3.x; a3.y += v3.y; a3.z += v3.z; a3.w += v3.w;
    }
    for (; p < np; p++) {
        float4 v = src[(size_t)p * len4 + i];
        a0.x += v.x; a0.y += v.y; a0.z += v.z; a0.w += v.w;
    }
    dst[i] = make_float4(a0.x + a1.x + a2.x + a3.x,
                         a0.y + a1.y + a2.y + a3.y,
                         a0.z + a1.z + a2.z + a3.z,
                         a0.w + a1.w + a2.w + a3.w);
}

// ======================= mini GEMM ===========================================
__global__ __launch_bounds__(256)
void smallgemm_kernel(const float* __restrict__ M64, const float* __restrict__ W)
{
    __shared__ float se[32][66];   // [e][m], padded
    const int tid = threadIdx.x;
    const int n0  = blockIdx.x * 64;
    const int e0  = blockIdx.y * 32;

    {
        const int m  = tid >> 2;
        const int ee = (tid & 3) * 8;
        const float* mp = M64 + (size_t)m * DD + e0 + ee;
        float4 v0 = *reinterpret_cast<const float4*>(mp);
        float4 v1 = *reinterpret_cast<const float4*>(mp + 4);
        se[ee + 0][m] = v0.x; se[ee + 1][m] = v0.y;
        se[ee + 2][m] = v0.z; se[ee + 3][m] = v0.w;
        se[ee + 4][m] = v1.x; se[ee + 5][m] = v1.y;
        se[ee + 6][m] = v1.z; se[ee + 7][m] = v1.w;
    }
    __syncthreads();

    const int nq = tid & 63;
    const int mg = tid >> 6;
    const float* wp = W + (size_t)e0 * DD + n0 + nq;

    ull acc[8];
    #pragma unroll
    for (int j = 0; j < 8; j++) acc[j] = 0ull;

    float wv[4], nv[4];
    #pragma unroll
    for (int q = 0; q < 4; q++) wv[q] = wp[(size_t)q * DD];

    #pragma unroll
    for (int e = 0; e < 32; e += 4) {
        if (e + 4 < 32) {
            #pragma unroll
            for (int q = 0; q < 4; q++) nv[q] = wp[(size_t)(e + 4 + q) * DD];
        }
        #pragma unroll
        for (int q = 0; q < 4; q++) {
            ull wd;
            PACK2(wd, wv[q], wv[q]);
            #pragma unroll
            for (int j = 0; j < 8; j++) {
                ull a = *reinterpret_cast<const ull*>(&se[e + q][mg * 16 + 2 * j]);
                FMA2(acc[j], a, wd);
            }
        }
        #pragma unroll
        for (int q = 0; q < 4; q++) wv[q] = nv[q];
    }

    float* dst = g_ssp + (size_t)blockIdx.y * MKD + n0 + nq;
    #pragma unroll
    for (int j = 0; j < 8; j++) {
        float2 p = *reinterpret_cast<float2*>(&acc[j]);
        dst[(size_t)(mg * 16 + 2 * j)     * DD] = p.x;
        dst[(size_t)(mg * 16 + 2 * j + 1) * DD] = p.y;
    }
}

// ======================= out = aff @ ssw (token-pair packed) =================
__global__ __launch_bounds__(256)
void out_mix_kernel(float* __restrict__ out)
{
    __shared__ float saT[KK][128];   // 8KB, aff transposed
    const int tid  = threadIdx.x;
    const int wid  = tid >> 5;
    const int lane = tid & 31;
    const int b    = blockIdx.y;
    const int s0   = blockIdx.x * 128;

    {
        const float* ap = g_aff + ((size_t)b * SS + s0) * KK;
        #pragma unroll
        for (int it = 0; it < 2; it++) {
            const int i = tid + it * 256;
            float4 v = *reinterpret_cast<const float4*>(ap + i * 4);
            const int t  = i >> 2;
            const int kg = (i & 3) * 4;
            saT[kg + 0][t] = v.x;
            saT[kg + 1][t] = v.y;
            saT[kg + 2][t] = v.z;
            saT[kg + 3][t] = v.w;
        }
    }
    __syncthreads();

    #pragma unroll 1
    for (int pass = 0; pass < 2; pass++) {
        const int d0 = pass * 512 + wid * 64 + lane * 2;

        ull wd0[KK], wd1[KK];
        #pragma unroll
        for (int k = 0; k < KK; k++) {
            float2 wv = *reinterpret_cast<const float2*>(
                g_ssw + ((size_t)(b * KK + k)) * DD + d0);
            PACK2(wd0[k], wv.x, wv.x);
            PACK2(wd1[k], wv.y, wv.y);
        }

        float* op = out + ((size_t)b * SS + s0) * DD + d0;

        #pragma unroll 2
        for (int t = 0; t < 128; t += 2) {
            ull acc0 = 0ull, acc1 = 0ull;
            #pragma unroll
            for (int k = 0; k < KK; k++) {
                ull a = *reinterpret_cast<const ull*>(&saT[k][t]);
                FMA2(acc0, a, wd0[k]);
                FMA2(acc1, a, wd1[k]);
            }
            float2 p0 = *reinterpret_cast<float2*>(&acc0);
            float2 p1 = *reinterpret_cast<float2*>(&acc1);
            *reinterpret_cast<float2*>(op + (size_t)t * DD)       = make_float2(p0.x, p1.x);
            *reinterpret_cast<float2*>(op + (size_t)(t + 1) * DD) = make_float2(p0.y, p1.y);
        }
    }
}

// ======================= launch ==============================================
extern "C" void kernel_launch(void* const* d_in, const int* in_sizes, int n_in,
                              void* d_out, int out_size)
{
    const float* tok     = (const float*)d_in[0];
    const float* centers = (const float*)d_in[1];
    const float* logs    = (const float*)d_in[2];
    const float* Wv      = (const float*)d_in[3];
    const float* Wo      = (const float*)d_in[4];
    float* out = (float*)d_out;

    float *tsp, *ts, *ssp, *ss, *ssw;
    cudaGetSymbolAddress((void**)&tsp, g_tsp);
    cudaGetSymbolAddress((void**)&ts,  g_ts);
    cudaGetSymbolAddress((void**)&ssp, g_ssp);
    cudaGetSymbolAddress((void**)&ss,  g_ss);
    cudaGetSymbolAddress((void**)&ssw, g_ssw);

    params_kernel<<<1, 512>>>(centers, logs);

    // affinities via tensor-pipe cross products
    cross_aff_kernel<<<MTOT / 128, 256>>>(tok, centers);

    // ts = aff^T @ tok (partials + reduce)
    ts_partial_kernel<<<dim3(TS_CHUNKS, BB), 256>>>(tok);
    reduce4_kernel<<<(MKD / 4 + 255) / 256, 256>>>(
        (const float4*)tsp, (float4*)ts, TS_CHUNKS, MKD / 4);

    // ss = ts @ W_v
    smallgemm_kernel<<<dim3(16, SG_ECHUNKS), 256>>>(ts, Wv);
    reduce4_kernel<<<(MKD / 4 + 255) / 256, 256>>>(
        (const float4*)ssp, (float4*)ss, SG_ECHUNKS, MKD / 4);

    // ssw = ss @ W_o
    smallgemm_kernel<<<dim3(16, SG_ECHUNKS), 256>>>(ss, Wo);
    reduce4_kernel<<<(MKD / 4 + 255) / 256, 256>>>(
        (const float4*)ssp, (float4*)ssw, SG_ECHUNKS, MKD / 4);

    // out = aff @ ssw
    out_mix_kernel<<<dim3(SS / 128, BB), 256>>>(out);
}

// round 11
// speedup vs baseline: 1.2667x; 1.0421x over previous
#include <cuda_runtime.h>
#include <cstdint>

// Problem constants
#define BB 4
#define SS 8192
#define DD 1024
#define KK 16
#define MTOT (BB * SS)        // 32768 tokens
#define TS_CHUNKS 64
#define TS_SLEN (SS / TS_CHUNKS)   // 128
#define MKD (BB * KK * DD)    // 65536
#define SG_ECHUNKS 32         // smallgemm e-chunks (32 e each)

// ---------------- scratch (device globals; no allocations) ------------------
__device__ float g_aff [(size_t)MTOT * KK];            // 2 MB
__device__ float g_tsp [(size_t)TS_CHUNKS * MKD];      // 16 MB  (ts partials)
__device__ float g_ts  [(size_t)MKD];                  // 256 KB (aff^T @ tok)
__device__ float g_ssp [(size_t)SG_ECHUNKS * MKD];     // 8 MB   (partials, reused)
__device__ float g_ss  [(size_t)MKD];                  // 256 KB (ts @ W_v)
__device__ float g_ssw [(size_t)MKD];                  // 256 KB (ss @ W_o)
__device__ float g_params[32];                         // csq[16], m[16]

// ---------------- packed f32x2 helpers ---------------------------------------
#define FMA2(d, a, b) \
    asm("fma.rn.f32x2 %0, %1, %2, %0;" : "+l"(d) : "l"(a), "l"(b))
#define PACK2(dst, lo, hi) \
    asm("mov.b64 %0, {%1, %2};" : "=l"(dst) \
        : "r"(__float_as_uint(lo)), "r"(__float_as_uint(hi)))

typedef unsigned long long ull;

__device__ __forceinline__ uint32_t smem_to_u32(const void* smem_ptr) {
    uint32_t addr;
    asm("{ .reg .u64 tmp; cvta.to.shared.u64 tmp, %1; cvt.u32.u64 %0, tmp; }"
        : "=r"(addr) : "l"(smem_ptr));
    return addr;
}
__device__ __forceinline__ uint32_t f2tf32(float x) {
    uint32_t r;
    asm("cvt.rn.tf32.f32 %0, %1;" : "=r"(r) : "f"(x));
    return r;
}
#define CP_ASYNC16(dst_u32, src_ptr) \
    asm volatile("cp.async.ca.shared.global [%0], [%1], 16;" \
        :: "r"(dst_u32), "l"(src_ptr) : "memory")
#define CP_COMMIT() asm volatile("cp.async.commit_group;" ::: "memory")
#define CP_WAIT1()  asm volatile("cp.async.wait_group 1;" ::: "memory")
#define CP_WAIT0()  asm volatile("cp.async.wait_group 0;" ::: "memory")

__device__ __forceinline__ void mma_tf32(float* c, const uint32_t* a, const uint32_t* b) {
    asm volatile(
        "mma.sync.aligned.m16n8k8.row.col.f32.tf32.tf32.f32 "
        "{%0,%1,%2,%3}, {%4,%5,%6,%7}, {%8,%9}, {%0,%1,%2,%3};\n"
        : "+f"(c[0]), "+f"(c[1]), "+f"(c[2]), "+f"(c[3])
        : "r"(a[0]), "r"(a[1]), "r"(a[2]), "r"(a[3]), "r"(b[0]), "r"(b[1]));
}

// ======================= kernel 0: per-splat params ==========================
__global__ __launch_bounds__(512)
void params_kernel(const float* __restrict__ centers,
                   const float* __restrict__ log_scales)
{
    const int w    = threadIdx.x >> 5;
    const int lane = threadIdx.x & 31;
    float s = 0.f;
    const float* c = centers + (size_t)w * DD;
    for (int d = lane; d < DD; d += 32) {
        float v = c[d];
        s = fmaf(v, v, s);
    }
    #pragma unroll
    for (int off = 16; off; off >>= 1)
        s += __shfl_xor_sync(0xffffffffu, s, off);
    if (lane == 0) {
        g_params[w] = s;
        float sc = expf(log_scales[w]);
        sc = fminf(fmaxf(sc, 0.1f), 2.0f);
        g_params[16 + w] = -0.5f / (sc * sc);
    }
}

// ======================= fused cross/aff (mma) + ts partials =================
// grid (TS_CHUNKS, BB), block 256 (8 warps). Block owns 128 tokens.
// Phase A: cross = tok @ centers^T via tf32 mma.sync; aff finalized in-register.
// Phase B: ts partial accumulation (token chunk re-read hits L2).
#define XLDP 36
#define XA_WORDS (128 * XLDP)          // 4608 floats
#define XB_WORDS (16 * XLDP)           // 576 floats
#define XBUF (XA_WORDS + XB_WORDS)     // 5184 floats = 20736 B per buffer

__global__ __launch_bounds__(256)
void fused_cross_aff_ts_kernel(const float* __restrict__ tok,
                               const float* __restrict__ centers)
{
    __shared__ float xs[2 * XBUF];     // 41472 B; aliased as saff after phase A
    float2 (*saff)[KK] = reinterpret_cast<float2(*)[KK]>(xs);  // [128][16] = 16KB

    const int tid  = threadIdx.x;
    const int w    = tid >> 5;
    const int lane = tid & 31;
    const int grp  = lane >> 2;        // 0..7
    const int tig  = lane & 3;         // 0..3
    const int ck   = blockIdx.x;
    const int b    = blockIdx.y;
    const int s0   = ck * TS_SLEN;
    const int bm   = b * SS + s0;      // global token base
    const int wm16 = w * 16;

    const uint32_t sbase = smem_to_u32(xs);

    // ---------------- Phase A: mma cross products ----------------
    float acc[2][4];
    #pragma unroll
    for (int nf = 0; nf < 2; nf++)
        #pragma unroll
        for (int q = 0; q < 4; q++) acc[nf][q] = 0.f;
    float sq0 = 0.f, sq1 = 0.f;

    {
        #pragma unroll
        for (int i = 0; i < 4; i++) {
            const int id  = tid + i * 256;
            const int row = id >> 3;
            const int c4  = id & 7;
            CP_ASYNC16(sbase + (uint32_t)(row * XLDP + c4 * 4) * 4,
                       tok + (size_t)(bm + row) * DD + c4 * 4);
        }
        if (tid < 128) {
            const int row = tid >> 3;
            const int c4  = tid & 7;
            CP_ASYNC16(sbase + (uint32_t)(XA_WORDS + row * XLDP + c4 * 4) * 4,
                       centers + (size_t)row * DD + c4 * 4);
        }
        CP_COMMIT();
    }

    for (int kc = 0; kc < DD / 32; kc++) {
        const int cur = kc & 1;
        if (kc + 1 < DD / 32) {
            const int nxt = cur ^ 1;
            const uint32_t nb = sbase + (uint32_t)nxt * XBUF * 4;
            const int k0 = (kc + 1) * 32;
            #pragma unroll
            for (int i = 0; i < 4; i++) {
                const int id  = tid + i * 256;
                const int row = id >> 3;
                const int c4  = id & 7;
                CP_ASYNC16(nb + (uint32_t)(row * XLDP + c4 * 4) * 4,
                           tok + (size_t)(bm + row) * DD + k0 + c4 * 4);
            }
            if (tid < 128) {
                const int row = tid >> 3;
                const int c4  = tid & 7;
                CP_ASYNC16(nb + (uint32_t)(XA_WORDS + row * XLDP + c4 * 4) * 4,
                           centers + (size_t)row * DD + k0 + c4 * 4);
            }
            CP_COMMIT();
            CP_WAIT1();
        } else {
            CP_WAIT0();
        }
        __syncthreads();

        const float* As = xs + (size_t)cur * XBUF;
        const float* Bs = As + XA_WORDS;

        #pragma unroll
        for (int ks = 0; ks < 4; ks++) {
            const int kq = ks * 8 + tig;
            const float a0 = As[(wm16 + grp)     * XLDP + kq];
            const float a1 = As[(wm16 + grp + 8) * XLDP + kq];
            const float a2 = As[(wm16 + grp)     * XLDP + kq + 4];
            const float a3 = As[(wm16 + grp + 8) * XLDP + kq + 4];
            sq0 = fmaf(a0, a0, fmaf(a2, a2, sq0));
            sq1 = fmaf(a1, a1, fmaf(a3, a3, sq1));
            uint32_t af[4] = {f2tf32(a0), f2tf32(a1), f2tf32(a2), f2tf32(a3)};
            #pragma unroll
            for (int nf = 0; nf < 2; nf++) {
                const int cidx = nf * 8 + grp;
                uint32_t bf[2] = {f2tf32(Bs[cidx * XLDP + kq]),
                                  f2tf32(Bs[cidx * XLDP + kq + 4])};
                mma_tf32(acc[nf], af, bf);
            }
        }
        __syncthreads();
    }

    // tsq: reduce over cols within each quad
    sq0 += __shfl_xor_sync(0xffffffffu, sq0, 1);
    sq0 += __shfl_xor_sync(0xffffffffu, sq0, 2);
    sq1 += __shfl_xor_sync(0xffffffffu, sq1, 1);
    sq1 += __shfl_xor_sync(0xffffffffu, sq1, 2);

    float e0[4], e1[4];
    #pragma unroll
    for (int nf = 0; nf < 2; nf++) {
        #pragma unroll
        for (int j = 0; j < 2; j++) {
            const int col = nf * 8 + tig * 2 + j;
            const float csq = g_params[col];
            const float m   = g_params[16 + col];
            float d0 = fmaxf(sq0 - 2.f * acc[nf][j]     + csq, 0.f);
            float d1 = fmaxf(sq1 - 2.f * acc[nf][2 + j] + csq, 0.f);
            e0[nf * 2 + j] = expf(m * d0);
            e1[nf * 2 + j] = expf(m * d1);
        }
    }
    float es0 = e0[0] + e0[1] + e0[2] + e0[3];
    float es1 = e1[0] + e1[1] + e1[2] + e1[3];
    es0 += __shfl_xor_sync(0xffffffffu, es0, 1);
    es0 += __shfl_xor_sync(0xffffffffu, es0, 2);
    es1 += __shfl_xor_sync(0xffffffffu, es1, 1);
    es1 += __shfl_xor_sync(0xffffffffu, es1, 2);
    const float r0 = 1.f / (es0 + 1e-8f);
    const float r1 = 1.f / (es1 + 1e-8f);

    // write aff to global + smem (aliased over dead xs)
    const int lt0 = wm16 + grp;            // local token 0..127
    #pragma unroll
    for (int nf = 0; nf < 2; nf++) {
        const int col = nf * 8 + tig * 2;
        float v00 = e0[nf * 2] * r0, v01 = e0[nf * 2 + 1] * r0;
        float v10 = e1[nf * 2] * r1, v11 = e1[nf * 2 + 1] * r1;
        *reinterpret_cast<float2*>(g_aff + (size_t)(bm + lt0) * KK + col) =
            make_float2(v00, v01);
        *reinterpret_cast<float2*>(g_aff + (size_t)(bm + lt0 + 8) * KK + col) =
            make_float2(v10, v11);
        saff[lt0][col]     = make_float2(v00, v00);
        saff[lt0][col + 1] = make_float2(v01, v01);
        saff[lt0 + 8][col]     = make_float2(v10, v10);
        saff[lt0 + 8][col + 1] = make_float2(v11, v11);
    }
    __syncthreads();

    // ---------------- Phase B: ts partial accumulation ----------------------
    const int d = tid * 4;
    const float* tp = tok + (size_t)bm * DD + d;

    ull tacc[KK][2];
    #pragma unroll
    for (int k = 0; k < KK; k++) { tacc[k][0] = 0ull; tacc[k][1] = 0ull; }

    #pragma unroll 2
    for (int s = 0; s < TS_SLEN; s++) {
        float4 v = *reinterpret_cast<const float4*>(tp + (size_t)s * DD);
        ull vlo, vhi;
        PACK2(vlo, v.x, v.y);
        PACK2(vhi, v.z, v.w);
        #pragma unroll
        for (int k = 0; k < KK; k++) {
            ull a = *reinterpret_cast<const ull*>(&saff[s][k]);
            FMA2(tacc[k][0], a, vlo);
            FMA2(tacc[k][1], a, vhi);
        }
    }

    float* op = g_tsp + (size_t)ck * MKD + ((size_t)b * KK) * DD + d;
    #pragma unroll
    for (int k = 0; k < KK; k++)
        *reinterpret_cast<ulonglong2*>(op + (size_t)k * DD) =
            make_ulonglong2(tacc[k][0], tacc[k][1]);
}

// ======================= reduce stage 1: 64 -> 8 partials ====================
// grid (len4/256, 8); block sums partials [pg*8, pg*8+8) -> g_ssp[pg]
__global__ __launch_bounds__(256)
void reduce_stage1_kernel(const float4* __restrict__ src, float4* __restrict__ dst,
                          int len4)
{
    const int i  = blockIdx.x * 256 + threadIdx.x;
    const int pg = blockIdx.y;
    float4 a0 = make_float4(0,0,0,0), a1 = a0;
    #pragma unroll
    for (int q = 0; q < 8; q += 2) {
        float4 v0 = src[(size_t)(pg * 8 + q)     * len4 + i];
        float4 v1 = src[(size_t)(pg * 8 + q + 1) * len4 + i];
        a0.x += v0.x; a0.y += v0.y; a0.z += v0.z; a0.w += v0.w;
        a1.x += v1.x; a1.y += v1.y; a1.z += v1.z; a1.w += v1.w;
    }
    dst[(size_t)pg * len4 + i] = make_float4(a0.x + a1.x, a0.y + a1.y,
                                             a0.z + a1.z, a0.w + a1.w);
}

// ======================= vectorized partial reduce ===========================
__global__ __launch_bounds__(256)
void reduce4_kernel(const float4* __restrict__ src, float4* __restrict__ dst,
                    int np, int len4)
{
    const int i = blockIdx.x * 256 + threadIdx.x;
    if (i >= len4) return;
    float4 a0 = make_float4(0,0,0,0), a1 = a0, a2 = a0, a3 = a0;
    int p = 0;
    for (; p + 4 <= np; p += 4) {
        float4 v0 = src[(size_t)(p + 0) * len4 + i];
        float4 v1 = src[(size_t)(p + 1) * len4 + i];
        float4 v2 = src[(size_t)(p + 2) * len4 + i];
        float4 v3 = src[(size_t)(p + 3) * len4 + i];
        a0.x += v0.x; a0.y += v0.y; a0.z += v0.z; a0.w += v0.w;
        a1.x += v1.x; a1.y += v1.y; a1.z += v1.z; a1.w += v1.w;
        a2.x += v2.x; a2.y += v2.y; a2.z += v2.z; a2.w += v2.w;
        a3.x += v3.x; a3.y += v3.y; a3.z += v3.z; a3.w += v3.w;
    }
    for (; p < np; p++) {
        float4 v = src[(size_t)p * len4 + i];
        a0.x += v.x; a0.y += v.y; a0.z += v.z; a0.w += v.w;
    }
    dst[i] = make_float4(a0.x + a1.x + a2.x + a3.x,
                         a0.y + a1.y + a2.y + a3.y,
                         a0.z + a1.z + a2.z + a3.z,
                         a0.w + a1.w + a2.w + a3.w);
}

// ======================= mini GEMM ===========================================
__global__ __launch_bounds__(256)
void smallgemm_kernel(const float* __restrict__ M64, const float* __restrict__ W)
{
    __shared__ float se[32][66];   // [e][m], padded
    const int tid = threadIdx.x;
    const int n0  = blockIdx.x * 64;
    const int e0  = blockIdx.y * 32;

    {
        const int m  = tid >> 2;
        const int ee = (tid & 3) * 8;
        const float* mp = M64 + (size_t)m * DD + e0 + ee;
        float4 v0 = *reinterpret_cast<const float4*>(mp);
        float4 v1 = *reinterpret_cast<const float4*>(mp + 4);
        se[ee + 0][m] = v0.x; se[ee + 1][m] = v0.y;
        se[ee + 2][m] = v0.z; se[ee + 3][m] = v0.w;
        se[ee + 4][m] = v1.x; se[ee + 5][m] = v1.y;
        se[ee + 6][m] = v1.z; se[ee + 7][m] = v1.w;
    }
    __syncthreads();

    const int nq = tid & 63;
    const int mg = tid >> 6;
    const float* wp = W + (size_t)e0 * DD + n0 + nq;

    ull acc[8];
    #pragma unroll
    for (int j = 0; j < 8; j++) acc[j] = 0ull;

    float wv[4], nv[4];
    #pragma unroll
    for (int q = 0; q < 4; q++) wv[q] = wp[(size_t)q * DD];

    #pragma unroll
    for (int e = 0; e < 32; e += 4) {
        if (e + 4 < 32) {
            #pragma unroll
            for (int q = 0; q < 4; q++) nv[q] = wp[(size_t)(e + 4 + q) * DD];
        }
        #pragma unroll
        for (int q = 0; q < 4; q++) {
            ull wd;
            PACK2(wd, wv[q], wv[q]);
            #pragma unroll
            for (int j = 0; j < 8; j++) {
                ull a = *reinterpret_cast<const ull*>(&se[e + q][mg * 16 + 2 * j]);
                FMA2(acc[j], a, wd);
            }
        }
        #pragma unroll
        for (int q = 0; q < 4; q++) wv[q] = nv[q];
    }

    float* dst = g_ssp + (size_t)blockIdx.y * MKD + n0 + nq;
    #pragma unroll
    for (int j = 0; j < 8; j++) {
        float2 p = *reinterpret_cast<float2*>(&acc[j]);
        dst[(size_t)(mg * 16 + 2 * j)     * DD] = p.x;
        dst[(size_t)(mg * 16 + 2 * j + 1) * DD] = p.y;
    }
}

// ======================= out = aff @ ssw (token-pair packed) =================
__global__ __launch_bounds__(256)
void out_mix_kernel(float* __restrict__ out)
{
    __shared__ float saT[KK][128];   // 8KB, aff transposed
    const int tid  = threadIdx.x;
    const int wid  = tid >> 5;
    const int lane = tid & 31;
    const int b    = blockIdx.y;
    const int s0   = blockIdx.x * 128;

    {
        const float* ap = g_aff + ((size_t)b * SS + s0) * KK;
        #pragma unroll
        for (int it = 0; it < 2; it++) {
            const int i = tid + it * 256;
            float4 v = *reinterpret_cast<const float4*>(ap + i * 4);
            const int t  = i >> 2;
            const int kg = (i & 3) * 4;
            saT[kg + 0][t] = v.x;
            saT[kg + 1][t] = v.y;
            saT[kg + 2][t] = v.z;
            saT[kg + 3][t] = v.w;
        }
    }
    __syncthreads();

    #pragma unroll 1
    for (int pass = 0; pass < 2; pass++) {
        const int d0 = pass * 512 + wid * 64 + lane * 2;

        ull wd0[KK], wd1[KK];
        #pragma unroll
        for (int k = 0; k < KK; k++) {
            float2 wv = *reinterpret_cast<const float2*>(
                g_ssw + ((size_t)(b * KK + k)) * DD + d0);
            PACK2(wd0[k], wv.x, wv.x);
            PACK2(wd1[k], wv.y, wv.y);
        }

        float* op = out + ((size_t)b * SS + s0) * DD + d0;

        #pragma unroll 2
        for (int t = 0; t < 128; t += 2) {
            ull acc0 = 0ull, acc1 = 0ull;
            #pragma unroll
            for (int k = 0; k < KK; k++) {
                ull a = *reinterpret_cast<const ull*>(&saT[k][t]);
                FMA2(acc0, a, wd0[k]);
                FMA2(acc1, a, wd1[k]);
            }
            float2 p0 = *reinterpret_cast<float2*>(&acc0);
            float2 p1 = *reinterpret_cast<float2*>(&acc1);
            *reinterpret_cast<float2*>(op + (size_t)t * DD)       = make_float2(p0.x, p1.x);
            *reinterpret_cast<float2*>(op + (size_t)(t + 1) * DD) = make_float2(p0.y, p1.y);
        }
    }
}

// ======================= launch ==============================================
extern "C" void kernel_launch(void* const* d_in, const int* in_sizes, int n_in,
                              void* d_out, int out_size)
{
    const float* tok     = (const float*)d_in[0];
    const float* centers = (const float*)d_in[1];
    const float* logs    = (const float*)d_in[2];
    const float* Wv      = (const float*)d_in[3];
    const float* Wo      = (const float*)d_in[4];
    float* out = (float*)d_out;

    float *tsp, *ts, *ssp, *ss, *ssw;
    cudaGetSymbolAddress((void**)&tsp, g_tsp);
    cudaGetSymbolAddress((void**)&ts,  g_ts);
    cudaGetSymbolAddress((void**)&ssp, g_ssp);
    cudaGetSymbolAddress((void**)&ss,  g_ss);
    cudaGetSymbolAddress((void**)&ssw, g_ssw);

    const int len4 = MKD / 4;   // 16384

    params_kernel<<<1, 512>>>(centers, logs);

    // affinities (mma) + ts partials, single token pass
    fused_cross_aff_ts_kernel<<<dim3(TS_CHUNKS, BB), 256>>>(tok, centers);

    // ts reduce: 64 -> 8 (into g_ssp) -> 1
    reduce_stage1_kernel<<<dim3(len4 / 256, 8), 256>>>(
        (const float4*)tsp, (float4*)ssp, len4);
    reduce4_kernel<<<len4 / 256, 256>>>(
        (const float4*)ssp, (float4*)ts, 8, len4);

    // ss = ts @ W_v
    smallgemm_kernel<<<dim3(16, SG_ECHUNKS), 256>>>(ts, Wv);
    reduce4_kernel<<<len4 / 256, 256>>>(
        (const float4*)ssp, (float4*)ss, SG_ECHUNKS, len4);

    // ssw = ss @ W_o
    smallgemm_kernel<<<dim3(16, SG_ECHUNKS), 256>>>(ss, Wo);
    reduce4_kernel<<<len4 / 256, 256>>>(
        (const float4*)ssp, (float4*)ssw, SG_ECHUNKS, len4);

    // out = aff @ ssw
    out_mix_kernel<<<dim3(SS / 128, BB), 256>>>(out);
}